// round 1
// baseline (speedup 1.0000x reference)
#include <cuda_runtime.h>
#include <math.h>

#define BB 4
#define NN 2048
#define TD 512
#define HH 128
#define RPB 16
#define CS 128
#define NC 16            // NN / CS
#define NP1 2049

// ---- scratch (static device globals; no allocation allowed) ----
__device__ float g_h[BB*NN*HH];        // layernormed h
__device__ float g_r[BB*NN];
__device__ float g_c[BB*NN];           // includes attn_b
__device__ float g_rs[BB*NN];          // sorted r
__device__ int   g_perm[BB*NN];
__device__ float g_F[BB*NN];           // exp(r'-rmax) sorted order
__device__ float g_f[BB*NN];           // exp(0.01(r'-rmax))
__device__ float g_Zpos[BB*NP1];
__device__ float g_Zneg[BB*NP1];
__device__ float g_Ppos[BB*NP1*HH];    // chunk-local suffix sums
__device__ float g_Pneg[BB*NP1*HH];    // chunk-local exclusive prefix sums
__device__ float g_Tpos[BB*NC*HH];
__device__ float g_Tneg[BB*NC*HH];
__device__ float g_OffPos[BB*(NC+1)*HH];
__device__ float g_OffNeg[BB*(NC+1)*HH];
__device__ float g_rmax[BB];

// ============================================================
// K1: h = LN(x @ fcw^T + fcb); r = h.w_row; c = h.w_col + b0
// grid: (B*N/RPB) blocks, 256 threads
// ============================================================
__global__ __launch_bounds__(256) void k_fc_ln(
    const float* __restrict__ x, const float* __restrict__ fcw,
    const float* __restrict__ fcb, const float* __restrict__ attw,
    const float* __restrict__ attb, const float* __restrict__ lng,
    const float* __restrict__ lnb)
{
    __shared__ __align__(16) float xs[RPB*TD];   // 32 KB
    __shared__ __align__(16) float hs[RPB*HH];   // 8 KB
    const int tid = threadIdx.x;
    const size_t row0 = (size_t)blockIdx.x * RPB;

    // cooperative load of 16 input rows (contiguous)
    const float4* xg = (const float4*)(x + row0 * TD);
    float4* xs4 = (float4*)xs;
    #pragma unroll
    for (int i = 0; i < (RPB*TD/4)/256; ++i) xs4[tid + i*256] = xg[tid + i*256];
    __syncthreads();

    const int k = tid & 127;    // output channel
    const int g = tid >> 7;     // row-group: rows g*8 .. g*8+7
    float acc[8];
    #pragma unroll
    for (int j = 0; j < 8; ++j) acc[j] = 0.f;

    const float4* wr4 = (const float4*)(fcw + (size_t)k * TD);
    const float4* xb  = xs4 + (g*8)*(TD/4);

    #pragma unroll 4
    for (int t4 = 0; t4 < TD/4; ++t4) {
        float4 w = __ldg(&wr4[t4]);
        #pragma unroll
        for (int j = 0; j < 8; ++j) {
            float4 v = xb[j*(TD/4) + t4];
            acc[j] = fmaf(w.x, v.x, acc[j]);
            acc[j] = fmaf(w.y, v.y, acc[j]);
            acc[j] = fmaf(w.z, v.z, acc[j]);
            acc[j] = fmaf(w.w, v.w, acc[j]);
        }
    }
    float bias = __ldg(&fcb[k]);
    #pragma unroll
    for (int j = 0; j < 8; ++j) hs[(g*8+j)*HH + k] = acc[j] + bias;
    __syncthreads();

    // LayerNorm + r/c dot products: warp w handles rows 2w, 2w+1
    const int wid = tid >> 5, lane = tid & 31;
    const float attb0 = __ldg(attb);
    const float4* lng4 = (const float4*)lng;
    const float4* lnb4 = (const float4*)lnb;
    const float4* wrv  = (const float4*)attw;          // w_row
    const float4* wcv  = (const float4*)(attw + HH);   // w_col

    #pragma unroll
    for (int rr = wid*2; rr < wid*2 + 2; ++rr) {
        float4 v = *(const float4*)&hs[rr*HH + lane*4];
        float s = v.x + v.y + v.z + v.w;
        #pragma unroll
        for (int o = 16; o; o >>= 1) s += __shfl_xor_sync(0xffffffffu, s, o);
        float mu = s * (1.0f/HH);
        float dx = v.x - mu, dy = v.y - mu, dz = v.z - mu, dw = v.w - mu;
        float q = dx*dx + dy*dy + dz*dz + dw*dw;
        #pragma unroll
        for (int o = 16; o; o >>= 1) q += __shfl_xor_sync(0xffffffffu, q, o);
        float rstd = rsqrtf(q * (1.0f/HH) + 1e-5f);
        float4 gg = __ldg(&lng4[lane]);
        float4 bb = __ldg(&lnb4[lane]);
        float4 n;
        n.x = fmaf(gg.x * dx, rstd, bb.x);
        n.y = fmaf(gg.y * dy, rstd, bb.y);
        n.z = fmaf(gg.z * dz, rstd, bb.z);
        n.w = fmaf(gg.w * dw, rstd, bb.w);
        *(float4*)&g_h[(row0 + rr)*HH + lane*4] = n;

        float4 a = __ldg(&wrv[lane]);
        float4 b2 = __ldg(&wcv[lane]);
        float rp = n.x*a.x + n.y*a.y + n.z*a.z + n.w*a.w;
        float cp = n.x*b2.x + n.y*b2.y + n.z*b2.z + n.w*b2.w;
        #pragma unroll
        for (int o = 16; o; o >>= 1) {
            rp += __shfl_xor_sync(0xffffffffu, rp, o);
            cp += __shfl_xor_sync(0xffffffffu, cp, o);
        }
        if (lane == 0) {
            g_r[row0 + rr] = rp;
            g_c[row0 + rr] = cp + attb0;
        }
    }
}

// ============================================================
// K2: per-batch rmax, bitonic sort of r (with perm), F/f, scalar Z scans
// grid: B blocks, 1024 threads
// ============================================================
__global__ __launch_bounds__(1024) void k_sort(void)
{
    __shared__ float sk[NN];
    __shared__ int   si[NN];
    __shared__ float bufA[NN];
    __shared__ float bufB[NN];
    __shared__ float red[32];
    const int b = blockIdx.x, tid = threadIdx.x;

    sk[tid]        = g_r[b*NN + tid];
    sk[tid + 1024] = g_r[b*NN + tid + 1024];
    si[tid] = tid; si[tid + 1024] = tid + 1024;
    __syncthreads();

    // rmax
    float m = fmaxf(sk[tid], sk[tid + 1024]);
    #pragma unroll
    for (int o = 16; o; o >>= 1) m = fmaxf(m, __shfl_xor_sync(0xffffffffu, m, o));
    if ((tid & 31) == 0) red[tid >> 5] = m;
    __syncthreads();
    if (tid < 32) {
        float mm = red[tid];
        #pragma unroll
        for (int o = 16; o; o >>= 1) mm = fmaxf(mm, __shfl_xor_sync(0xffffffffu, mm, o));
        if (tid == 0) { red[0] = mm; g_rmax[b] = mm; }
    }
    __syncthreads();
    const float rmax = red[0];

    // bitonic sort ascending (key=r, value=index)
    for (int kk = 2; kk <= NN; kk <<= 1) {
        for (int j = kk >> 1; j > 0; j >>= 1) {
            __syncthreads();
            #pragma unroll 1
            for (int i = tid; i < NN; i += 1024) {
                int ixj = i ^ j;
                if (ixj > i) {
                    float a = sk[i], bq = sk[ixj];
                    bool up = ((i & kk) == 0);
                    if ((a > bq) == up) {
                        sk[i] = bq; sk[ixj] = a;
                        int t = si[i]; si[i] = si[ixj]; si[ixj] = t;
                    }
                }
            }
        }
    }
    __syncthreads();

    // F, f + stage f for Zneg scan
    #pragma unroll 1
    for (int i = tid; i < NN; i += 1024) {
        float rv = sk[i];
        g_rs[b*NN + i]   = rv;
        g_perm[b*NN + i] = si[i];
        float Fv = expf(rv - rmax);
        float fv = expf(0.01f * (rv - rmax));
        g_F[b*NN + i] = Fv;
        g_f[b*NN + i] = fv;
        bufA[i] = fv;
    }

    // scan 1: inclusive prefix of f -> Zneg (exclusive, length NN+1)
    {
        float* src = bufA; float* dst = bufB;
        for (int off = 1; off < NN; off <<= 1) {
            __syncthreads();
            #pragma unroll 1
            for (int i = tid; i < NN; i += 1024)
                dst[i] = src[i] + ((i >= off) ? src[i - off] : 0.f);
            float* t = src; src = dst; dst = t;
        }
        __syncthreads();
        #pragma unroll 1
        for (int i = tid; i < NN; i += 1024) g_Zneg[b*NP1 + i + 1] = src[i];
        if (tid == 0) g_Zneg[b*NP1] = 0.f;
    }
    __syncthreads();

    // scan 2: reversed F -> Zpos (inclusive suffix, Zpos[NN]=0)
    #pragma unroll 1
    for (int i = tid; i < NN; i += 1024) bufA[i] = expf(sk[NN-1-i] - rmax);
    {
        float* src = bufA; float* dst = bufB;
        for (int off = 1; off < NN; off <<= 1) {
            __syncthreads();
            #pragma unroll 1
            for (int i = tid; i < NN; i += 1024)
                dst[i] = src[i] + ((i >= off) ? src[i - off] : 0.f);
            float* t = src; src = dst; dst = t;
        }
        __syncthreads();
        #pragma unroll 1
        for (int i = tid; i < NN; i += 1024) g_Zpos[b*NP1 + (NN-1-i)] = src[i];
        if (tid == 0) g_Zpos[b*NP1 + NN] = 0.f;
    }
}

// ============================================================
// K3a: chunk-local vector scans. grid (NC, B), 256 threads
//   tid<128: ascending exclusive prefix with f  -> Pneg local
//   tid>=128: descending inclusive suffix with F -> Ppos local
// ============================================================
__global__ __launch_bounds__(256) void k_scan(void)
{
    __shared__ int   sp[CS];
    __shared__ float sF[CS];
    __shared__ float sf[CS];
    const int c = blockIdx.x, b = blockIdx.y, tid = threadIdx.x;
    const int ub = b*NN + c*CS;
    if (tid < CS) {
        sp[tid] = g_perm[ub + tid];
        sF[tid] = g_F[ub + tid];
        sf[tid] = g_f[ub + tid];
    }
    __syncthreads();

    const float* hb = g_h + (size_t)b * NN * HH;
    const int k = tid & 127;
    const size_t base = ((size_t)(b*NP1) + (size_t)c*CS) * HH + k;

    if (tid < 128) {
        float acc = 0.f;
        #pragma unroll 1
        for (int v0 = 0; v0 < CS; v0 += 8) {
            float hv[8];
            #pragma unroll
            for (int q = 0; q < 8; ++q) hv[q] = __ldg(hb + (size_t)sp[v0+q]*HH + k);
            #pragma unroll
            for (int q = 0; q < 8; ++q) {
                g_Pneg[base + (size_t)(v0+q)*HH] = acc;
                acc = fmaf(sf[v0+q], hv[q], acc);
            }
        }
        g_Tneg[(b*NC + c)*HH + k] = acc;
    } else {
        float acc = 0.f;
        #pragma unroll 1
        for (int v0 = 0; v0 < CS; v0 += 8) {
            float hv[8];
            #pragma unroll
            for (int q = 0; q < 8; ++q) {
                int vv = CS-1-(v0+q);
                hv[q] = __ldg(hb + (size_t)sp[vv]*HH + k);
            }
            #pragma unroll
            for (int q = 0; q < 8; ++q) {
                int vv = CS-1-(v0+q);
                acc = fmaf(sF[vv], hv[q], acc);
                g_Ppos[base + (size_t)vv*HH] = acc;
            }
        }
        g_Tpos[(b*NC + c)*HH + k] = acc;
    }
}

// ============================================================
// K3b: chunk offsets + boundary rows. grid B, 256 threads
// ============================================================
__global__ __launch_bounds__(256) void k_off(void)
{
    const int b = blockIdx.x, tid = threadIdx.x;
    const int k = tid & 127;
    if (tid < 128) {
        float acc = 0.f;
        #pragma unroll
        for (int c = 0; c < NC; ++c) {
            g_OffNeg[(b*(NC+1) + c)*HH + k] = acc;
            acc += g_Tneg[(b*NC + c)*HH + k];
        }
        g_OffNeg[(b*(NC+1) + NC)*HH + k] = acc;
        g_Pneg[((size_t)(b*NP1) + NN)*HH + k] = 0.f;
    } else {
        float acc = 0.f;
        g_OffPos[(b*(NC+1) + NC)*HH + k] = 0.f;
        #pragma unroll
        for (int c = NC-1; c >= 0; --c) {
            g_OffPos[(b*(NC+1) + c)*HH + k] = acc;
            acc += g_Tpos[(b*NC + c)*HH + k];
        }
        g_Ppos[((size_t)(b*NP1) + NN)*HH + k] = 0.f;
    }
}

// ============================================================
// K4: output. grid B*N blocks, 128 threads (one row each)
// ============================================================
__global__ __launch_bounds__(128) void k_out(float* __restrict__ out)
{
    const int row = blockIdx.x;
    const int b = row >> 11;
    const int k = threadIdx.x;

    const float cv   = g_c[row];
    const float rmax = g_rmax[b];
    const float* rs  = g_rs + b*NN;
    const float thr  = -cv;

    // first t with rs[t] >= -cv  (pos set = suffix from t)
    int lo = 0, hi = NN;
    while (lo < hi) {
        int mid = (lo + hi) >> 1;
        if (rs[mid] < thr) lo = mid + 1; else hi = mid;
    }
    const int t = lo;

    const float a1 = cv + rmax;
    const float S  = fmaxf(a1, 0.f);
    const float E  = expf(a1 - S);
    const float e2 = expf(fmaf(0.01f, a1, -S));
    const float den = E * g_Zpos[b*NP1 + t] + e2 * g_Zneg[b*NP1 + t];
    const float inv = 1.0f / den;
    const float cA = E * inv, cB = e2 * inv;

    const int ch = t >> 7;  // chunk index, 0..NC (t==NN -> NC)
    const size_t base = ((size_t)(b*NP1) + t) * HH + k;
    const int obase = (b*(NC+1) + ch)*HH + k;
    const float pp = g_Ppos[base] + g_OffPos[obase];
    const float pn = g_Pneg[base] + g_OffNeg[obase];
    out[(size_t)row*HH + k] = fmaf(cA, pp, cB * pn);
}

// ============================================================
extern "C" void kernel_launch(void* const* d_in, const int* in_sizes, int n_in,
                              void* d_out, int out_size)
{
    const float* x    = (const float*)d_in[0];  // token_embedding (B,N,TD)
    const float* fcw  = (const float*)d_in[1];  // (HH, TD)
    const float* fcb  = (const float*)d_in[2];  // (HH,)
    const float* attw = (const float*)d_in[3];  // (1, 2*HH)
    const float* attb = (const float*)d_in[4];  // (1,)
    const float* lng  = (const float*)d_in[5];  // (HH,)
    const float* lnb  = (const float*)d_in[6];  // (HH,)
    float* out = (float*)d_out;

    k_fc_ln<<<(BB*NN)/RPB, 256>>>(x, fcw, fcb, attw, attb, lng, lnb);
    k_sort<<<BB, 1024>>>();
    k_scan<<<dim3(NC, BB), 256>>>();
    k_off<<<BB, 256>>>();
    k_out<<<BB*NN, 128>>>(out);
}

// round 2
// speedup vs baseline: 1.7476x; 1.7476x over previous
#include <cuda_runtime.h>
#include <math.h>

#define BB 4
#define NN 2048
#define TD 512
#define HH 128
#define RPB 16
#define CS 64
#define NC 32            // NN / CS
#define NP1 2049

// ---- scratch (static device globals; no allocation allowed) ----
__device__ float4 g_wt[(TD/4)*HH];     // transposed fc weights: [t4][k] = w[k][4t4..4t4+3]
__device__ float g_h[BB*NN*HH];        // layernormed h
__device__ float g_r[BB*NN];
__device__ float g_c[BB*NN];           // includes attn_b
__device__ float g_rs[BB*NN];          // sorted r
__device__ int   g_perm[BB*NN];
__device__ float g_F[BB*NN];           // exp(r'-rmax) sorted order
__device__ float g_f[BB*NN];           // exp(0.01(r'-rmax))
__device__ float g_Zpos[BB*NP1];
__device__ float g_Zneg[BB*NP1];
__device__ float g_Ppos[BB*NP1*HH];    // chunk-local suffix sums
__device__ float g_Pneg[BB*NP1*HH];    // chunk-local exclusive prefix sums
__device__ float g_Tpos[BB*NC*HH];
__device__ float g_Tneg[BB*NC*HH];
__device__ float g_OffPos[BB*(NC+1)*HH];
__device__ float g_OffNeg[BB*(NC+1)*HH];
__device__ float g_rmax[BB];

// ============================================================
// K0: transpose fcw (HH x TD) -> g_wt[t4][k] (float4 per (t4,k))
// grid (4,4), block (32,8)
// ============================================================
__global__ __launch_bounds__(256) void k_wt(const float* __restrict__ fcw)
{
    __shared__ float4 tile[32][33];
    const int tx = threadIdx.x, ty = threadIdx.y;
    const int t4_0 = blockIdx.x * 32;
    const int k_0  = blockIdx.y * 32;
    const float4* w4 = (const float4*)fcw;   // [k][TD/4]
    #pragma unroll
    for (int i = 0; i < 4; ++i) {
        int k = k_0 + ty + i*8;
        tile[ty + i*8][tx] = w4[(size_t)k*(TD/4) + (t4_0 + tx)];
    }
    __syncthreads();
    #pragma unroll
    for (int i = 0; i < 4; ++i) {
        int t4 = t4_0 + ty + i*8;
        g_wt[(size_t)t4*HH + (k_0 + tx)] = tile[tx][ty + i*8];
    }
}

// ============================================================
// K1: h = LN(x @ fcw^T + fcb); r = h.w_row; c = h.w_col + b0
// grid: (B*N/RPB) blocks, 256 threads
// w loads coalesced via g_wt; x loads warp-broadcast from smem.
// ============================================================
__global__ __launch_bounds__(256) void k_fc_ln(
    const float* __restrict__ x,
    const float* __restrict__ fcb, const float* __restrict__ attw,
    const float* __restrict__ attb, const float* __restrict__ lng,
    const float* __restrict__ lnb)
{
    __shared__ __align__(16) float xs[RPB*TD];   // 32 KB
    __shared__ __align__(16) float hs[RPB*HH];   // 8 KB
    const int tid = threadIdx.x;
    const size_t row0 = (size_t)blockIdx.x * RPB;

    // cooperative load of 16 input rows (contiguous)
    const float4* xg = (const float4*)(x + row0 * TD);
    float4* xs4 = (float4*)xs;
    #pragma unroll
    for (int i = 0; i < (RPB*TD/4)/256; ++i) xs4[tid + i*256] = xg[tid + i*256];
    __syncthreads();

    const int k = tid & 127;    // output channel; warp lanes = consecutive k
    const int g = tid >> 7;     // row-group: rows g*8 .. g*8+7
    float acc[8];
    #pragma unroll
    for (int j = 0; j < 8; ++j) acc[j] = 0.f;

    const float4* wp = g_wt + k;             // stride HH float4s per t4
    const float4* xb = xs4 + (g*8)*(TD/4);

    #pragma unroll 4
    for (int t4 = 0; t4 < TD/4; ++t4) {
        float4 w = __ldg(&wp[(size_t)t4*HH]);   // coalesced 512B per warp
        #pragma unroll
        for (int j = 0; j < 8; ++j) {
            float4 v = xb[j*(TD/4) + t4];       // warp-broadcast LDS.128
            acc[j] = fmaf(w.x, v.x, acc[j]);
            acc[j] = fmaf(w.y, v.y, acc[j]);
            acc[j] = fmaf(w.z, v.z, acc[j]);
            acc[j] = fmaf(w.w, v.w, acc[j]);
        }
    }
    float bias = __ldg(&fcb[k]);
    #pragma unroll
    for (int j = 0; j < 8; ++j) hs[(g*8+j)*HH + k] = acc[j] + bias;
    __syncthreads();

    // LayerNorm + r/c dot products: warp w handles rows 2w, 2w+1
    const int wid = tid >> 5, lane = tid & 31;
    const float attb0 = __ldg(attb);
    const float4* lng4 = (const float4*)lng;
    const float4* lnb4 = (const float4*)lnb;
    const float4* wrv  = (const float4*)attw;          // w_row
    const float4* wcv  = (const float4*)(attw + HH);   // w_col

    #pragma unroll
    for (int rr = wid*2; rr < wid*2 + 2; ++rr) {
        float4 v = *(const float4*)&hs[rr*HH + lane*4];
        float s = v.x + v.y + v.z + v.w;
        #pragma unroll
        for (int o = 16; o; o >>= 1) s += __shfl_xor_sync(0xffffffffu, s, o);
        float mu = s * (1.0f/HH);
        float dx = v.x - mu, dy = v.y - mu, dz = v.z - mu, dw = v.w - mu;
        float q = dx*dx + dy*dy + dz*dz + dw*dw;
        #pragma unroll
        for (int o = 16; o; o >>= 1) q += __shfl_xor_sync(0xffffffffu, q, o);
        float rstd = rsqrtf(q * (1.0f/HH) + 1e-5f);
        float4 gg = __ldg(&lng4[lane]);
        float4 bb = __ldg(&lnb4[lane]);
        float4 n;
        n.x = fmaf(gg.x * dx, rstd, bb.x);
        n.y = fmaf(gg.y * dy, rstd, bb.y);
        n.z = fmaf(gg.z * dz, rstd, bb.z);
        n.w = fmaf(gg.w * dw, rstd, bb.w);
        *(float4*)&g_h[(row0 + rr)*HH + lane*4] = n;

        float4 a = __ldg(&wrv[lane]);
        float4 b2 = __ldg(&wcv[lane]);
        float rp = n.x*a.x + n.y*a.y + n.z*a.z + n.w*a.w;
        float cp = n.x*b2.x + n.y*b2.y + n.z*b2.z + n.w*b2.w;
        #pragma unroll
        for (int o = 16; o; o >>= 1) {
            rp += __shfl_xor_sync(0xffffffffu, rp, o);
            cp += __shfl_xor_sync(0xffffffffu, cp, o);
        }
        if (lane == 0) {
            g_r[row0 + rr] = rp;
            g_c[row0 + rr] = cp + attb0;
        }
    }
}

// ============================================================
// K2: per-batch rmax, bitonic sort (packed u64 key|idx), F/f, scalar Z scans
// grid: B blocks, 1024 threads
// ============================================================
__device__ __forceinline__ unsigned int f2mono(float f) {
    unsigned int u = __float_as_uint(f);
    return (u & 0x80000000u) ? ~u : (u | 0x80000000u);
}
__device__ __forceinline__ float mono2f(unsigned int u) {
    unsigned int b = (u & 0x80000000u) ? (u ^ 0x80000000u) : ~u;
    return __uint_as_float(b);
}

__global__ __launch_bounds__(1024) void k_sort(void)
{
    __shared__ unsigned long long skk[NN];   // 16 KB: key<<32 | idx
    __shared__ float bufA[NN];
    __shared__ float bufB[NN];
    __shared__ float red[32];
    const int b = blockIdx.x, tid = threadIdx.x;

    float r0 = g_r[b*NN + tid];
    float r1 = g_r[b*NN + tid + 1024];
    skk[tid]        = ((unsigned long long)f2mono(r0) << 32) | (unsigned int)tid;
    skk[tid + 1024] = ((unsigned long long)f2mono(r1) << 32) | (unsigned int)(tid + 1024);
    __syncthreads();

    // rmax
    float m = fmaxf(r0, r1);
    #pragma unroll
    for (int o = 16; o; o >>= 1) m = fmaxf(m, __shfl_xor_sync(0xffffffffu, m, o));
    if ((tid & 31) == 0) red[tid >> 5] = m;
    __syncthreads();
    if (tid < 32) {
        float mm = red[tid];
        #pragma unroll
        for (int o = 16; o; o >>= 1) mm = fmaxf(mm, __shfl_xor_sync(0xffffffffu, mm, o));
        if (tid == 0) { red[0] = mm; g_rmax[b] = mm; }
    }
    __syncthreads();
    const float rmax = red[0];

    // bitonic sort ascending on packed u64
    for (int kk = 2; kk <= NN; kk <<= 1) {
        for (int j = kk >> 1; j > 0; j >>= 1) {
            __syncthreads();
            #pragma unroll 1
            for (int i = tid; i < NN; i += 1024) {
                int ixj = i ^ j;
                if (ixj > i) {
                    unsigned long long a = skk[i], bq = skk[ixj];
                    bool up = ((i & kk) == 0);
                    if ((a > bq) == up) { skk[i] = bq; skk[ixj] = a; }
                }
            }
        }
    }
    __syncthreads();

    // decode, F, f + stage f for Zneg scan
    #pragma unroll 1
    for (int i = tid; i < NN; i += 1024) {
        unsigned long long p = skk[i];
        float rv = mono2f((unsigned int)(p >> 32));
        g_rs[b*NN + i]   = rv;
        g_perm[b*NN + i] = (int)(unsigned int)(p & 0xffffffffu);
        float Fv = expf(rv - rmax);
        float fv = expf(0.01f * (rv - rmax));
        g_F[b*NN + i] = Fv;
        g_f[b*NN + i] = fv;
        bufA[i] = fv;
    }

    // scan 1: inclusive prefix of f -> Zneg (exclusive, length NN+1)
    {
        float* src = bufA; float* dst = bufB;
        for (int off = 1; off < NN; off <<= 1) {
            __syncthreads();
            #pragma unroll 1
            for (int i = tid; i < NN; i += 1024)
                dst[i] = src[i] + ((i >= off) ? src[i - off] : 0.f);
            float* t = src; src = dst; dst = t;
        }
        __syncthreads();
        #pragma unroll 1
        for (int i = tid; i < NN; i += 1024) g_Zneg[b*NP1 + i + 1] = src[i];
        if (tid == 0) g_Zneg[b*NP1] = 0.f;
    }
    __syncthreads();

    // scan 2: reversed F -> Zpos (inclusive suffix, Zpos[NN]=0)
    #pragma unroll 1
    for (int i = tid; i < NN; i += 1024) bufA[i] = g_F[b*NN + (NN-1-i)];
    {
        float* src = bufA; float* dst = bufB;
        for (int off = 1; off < NN; off <<= 1) {
            __syncthreads();
            #pragma unroll 1
            for (int i = tid; i < NN; i += 1024)
                dst[i] = src[i] + ((i >= off) ? src[i - off] : 0.f);
            float* t = src; src = dst; dst = t;
        }
        __syncthreads();
        #pragma unroll 1
        for (int i = tid; i < NN; i += 1024) g_Zpos[b*NP1 + (NN-1-i)] = src[i];
        if (tid == 0) g_Zpos[b*NP1 + NN] = 0.f;
    }
}

// ============================================================
// K3a: chunk-local vector scans. grid (NC, B), 256 threads
// ============================================================
__global__ __launch_bounds__(256) void k_scan(void)
{
    __shared__ int   sp[CS];
    __shared__ float sF[CS];
    __shared__ float sf[CS];
    const int c = blockIdx.x, b = blockIdx.y, tid = threadIdx.x;
    const int ub = b*NN + c*CS;
    if (tid < CS) {
        sp[tid] = g_perm[ub + tid];
        sF[tid] = g_F[ub + tid];
        sf[tid] = g_f[ub + tid];
    }
    __syncthreads();

    const float* hb = g_h + (size_t)b * NN * HH;
    const int k = tid & 127;
    const size_t base = ((size_t)(b*NP1) + (size_t)c*CS) * HH + k;

    if (tid < 128) {
        float acc = 0.f;
        #pragma unroll 1
        for (int v0 = 0; v0 < CS; v0 += 8) {
            float hv[8];
            #pragma unroll
            for (int q = 0; q < 8; ++q) hv[q] = __ldg(hb + (size_t)sp[v0+q]*HH + k);
            #pragma unroll
            for (int q = 0; q < 8; ++q) {
                g_Pneg[base + (size_t)(v0+q)*HH] = acc;
                acc = fmaf(sf[v0+q], hv[q], acc);
            }
        }
        g_Tneg[(b*NC + c)*HH + k] = acc;
    } else {
        float acc = 0.f;
        #pragma unroll 1
        for (int v0 = 0; v0 < CS; v0 += 8) {
            float hv[8];
            #pragma unroll
            for (int q = 0; q < 8; ++q) {
                int vv = CS-1-(v0+q);
                hv[q] = __ldg(hb + (size_t)sp[vv]*HH + k);
            }
            #pragma unroll
            for (int q = 0; q < 8; ++q) {
                int vv = CS-1-(v0+q);
                acc = fmaf(sF[vv], hv[q], acc);
                g_Ppos[base + (size_t)vv*HH] = acc;
            }
        }
        g_Tpos[(b*NC + c)*HH + k] = acc;
    }
}

// ============================================================
// K3b: chunk offsets + boundary rows. grid B, 256 threads.
// Batched loads (MLP=NC) then register prefix.
// ============================================================
__global__ __launch_bounds__(256) void k_off(void)
{
    const int b = blockIdx.x, tid = threadIdx.x;
    const int k = tid & 127;
    if (tid < 128) {
        float tv[NC];
        #pragma unroll
        for (int c = 0; c < NC; ++c) tv[c] = g_Tneg[(b*NC + c)*HH + k];
        float acc = 0.f;
        #pragma unroll
        for (int c = 0; c < NC; ++c) {
            g_OffNeg[(b*(NC+1) + c)*HH + k] = acc;
            acc += tv[c];
        }
        g_OffNeg[(b*(NC+1) + NC)*HH + k] = acc;
        g_Pneg[((size_t)(b*NP1) + NN)*HH + k] = 0.f;
    } else {
        float tv[NC];
        #pragma unroll
        for (int c = 0; c < NC; ++c) tv[c] = g_Tpos[(b*NC + c)*HH + k];
        float acc = 0.f;
        g_OffPos[(b*(NC+1) + NC)*HH + k] = 0.f;
        #pragma unroll
        for (int c = NC-1; c >= 0; --c) {
            g_OffPos[(b*(NC+1) + c)*HH + k] = acc;
            acc += tv[c];
        }
        g_Ppos[((size_t)(b*NP1) + NN)*HH + k] = 0.f;
    }
}

// ============================================================
// K4: output. grid B*N blocks, 128 threads (one row each)
// ============================================================
__global__ __launch_bounds__(128) void k_out(float* __restrict__ out)
{
    const int row = blockIdx.x;
    const int b = row >> 11;
    const int k = threadIdx.x;

    const float cv   = g_c[row];
    const float rmax = g_rmax[b];
    const float* rs  = g_rs + b*NN;
    const float thr  = -cv;

    // first t with rs[t] >= -cv  (pos set = suffix from t)
    int lo = 0, hi = NN;
    while (lo < hi) {
        int mid = (lo + hi) >> 1;
        if (rs[mid] < thr) lo = mid + 1; else hi = mid;
    }
    const int t = lo;

    const float a1 = cv + rmax;
    const float S  = fmaxf(a1, 0.f);
    const float E  = expf(a1 - S);
    const float e2 = expf(fmaf(0.01f, a1, -S));
    const float den = E * g_Zpos[b*NP1 + t] + e2 * g_Zneg[b*NP1 + t];
    const float inv = 1.0f / den;
    const float cA = E * inv, cB = e2 * inv;

    const int ch = t / CS;  // chunk index, 0..NC (t==NN -> NC)
    const size_t base = ((size_t)(b*NP1) + t) * HH + k;
    const int obase = (b*(NC+1) + ch)*HH + k;
    const float pp = g_Ppos[base] + g_OffPos[obase];
    const float pn = g_Pneg[base] + g_OffNeg[obase];
    out[(size_t)row*HH + k] = fmaf(cA, pp, cB * pn);
}

// ============================================================
extern "C" void kernel_launch(void* const* d_in, const int* in_sizes, int n_in,
                              void* d_out, int out_size)
{
    const float* x    = (const float*)d_in[0];  // token_embedding (B,N,TD)
    const float* fcw  = (const float*)d_in[1];  // (HH, TD)
    const float* fcb  = (const float*)d_in[2];  // (HH,)
    const float* attw = (const float*)d_in[3];  // (1, 2*HH)
    const float* attb = (const float*)d_in[4];  // (1,)
    const float* lng  = (const float*)d_in[5];  // (HH,)
    const float* lnb  = (const float*)d_in[6];  // (HH,)
    float* out = (float*)d_out;

    k_wt<<<dim3(4,4), dim3(32,8)>>>(fcw);
    k_fc_ln<<<(BB*NN)/RPB, 256>>>(x, fcb, attw, attb, lng, lnb);
    k_sort<<<BB, 1024>>>();
    k_scan<<<dim3(NC, BB), 256>>>();
    k_off<<<BB, 256>>>();
    k_out<<<BB*NN, 128>>>(out);
}

// round 4
// speedup vs baseline: 2.0097x; 1.1500x over previous
#include <cuda_runtime.h>
#include <math.h>

#define BB 4
#define NN 2048
#define TD 512
#define HH 128
#define RPB 16
#define CS 32
#define NC 64            // NN / CS
#define NP1 2049

// ---- scratch (static device globals; no allocation allowed) ----
__device__ float4 g_wt[(TD/4)*HH];     // transposed fc weights: [t4][k]
__device__ float g_h[BB*NN*HH];
__device__ float g_r[BB*NN];
__device__ float g_c[BB*NN];
__device__ float g_rs[BB*NN];
__device__ int   g_perm[BB*NN];
__device__ float g_F[BB*NN];
__device__ float g_f[BB*NN];
__device__ float g_Zpos[BB*NP1];
__device__ float g_Zneg[BB*NP1];
__device__ float g_Ppos[BB*NP1*HH];
__device__ float g_Pneg[BB*NP1*HH];
__device__ float g_Tpos[BB*NC*HH];
__device__ float g_Tneg[BB*NC*HH];
__device__ float g_OffPos[BB*(NC+1)*HH];
__device__ float g_OffNeg[BB*(NC+1)*HH];
__device__ float g_rmax[BB];

// ---- f32x2 helpers ----
__device__ __forceinline__ unsigned long long f2x2_dup(float w) {
    unsigned long long r;
    asm("mov.b64 %0, {%1, %1};" : "=l"(r) : "f"(w));
    return r;
}
__device__ __forceinline__ unsigned long long f2x2_pack(float lo, float hi) {
    unsigned long long r;
    asm("mov.b64 %0, {%1, %2};" : "=l"(r) : "f"(lo), "f"(hi));
    return r;
}
__device__ __forceinline__ void f2x2_unpack(unsigned long long v, float& lo, float& hi) {
    asm("mov.b64 {%0, %1}, %2;" : "=f"(lo), "=f"(hi) : "l"(v));
}
__device__ __forceinline__ void f2x2_fma(unsigned long long& d,
                                         unsigned long long a, unsigned long long b) {
    asm("fma.rn.f32x2 %0, %1, %2, %0;" : "+l"(d) : "l"(a), "l"(b));
}

// ============================================================
// K0: transpose fcw (HH x TD) -> g_wt[t4][k]
// ============================================================
__global__ __launch_bounds__(256) void k_wt(const float* __restrict__ fcw)
{
    __shared__ float4 tile[32][33];
    const int tx = threadIdx.x, ty = threadIdx.y;
    const int t4_0 = blockIdx.x * 32;
    const int k_0  = blockIdx.y * 32;
    const float4* w4 = (const float4*)fcw;
    #pragma unroll
    for (int i = 0; i < 4; ++i) {
        int k = k_0 + ty + i*8;
        tile[ty + i*8][tx] = w4[(size_t)k*(TD/4) + (t4_0 + tx)];
    }
    __syncthreads();
    #pragma unroll
    for (int i = 0; i < 4; ++i) {
        int t4 = t4_0 + ty + i*8;
        g_wt[(size_t)t4*HH + (k_0 + tx)] = tile[tx][ty + i*8];
    }
}

// ============================================================
// K1: h = LN(x @ fcw^T + fcb); r, c.  FFMA2 (f32x2) mainloop.
// grid: (B*N/RPB) blocks, 256 threads.
// x staged transposed as row-pairs: xst2[t*9 + p] = (x[2p][t], x[2p+1][t])
// ============================================================
__global__ __launch_bounds__(256) void k_fc_ln(
    const float* __restrict__ x,
    const float* __restrict__ fcb, const float* __restrict__ attw,
    const float* __restrict__ attb, const float* __restrict__ lng,
    const float* __restrict__ lnb)
{
    __shared__ __align__(16) unsigned long long xst2[TD*9];  // 36864 B (8 pairs + 1 pad per t)
    __shared__ __align__(16) float hs[RPB*HH];               // 8 KB
    const int tid = threadIdx.x;
    const size_t row0 = (size_t)blockIdx.x * RPB;
    const float* xb = x + row0 * TD;

    // staging: 4096 float2 elements; fi -> t = fi&511, p = fi>>9 (coalesced LDG)
    #pragma unroll
    for (int i = 0; i < 16; ++i) {
        int fi = tid + (i << 8);
        int t = fi & 511, p = fi >> 9;
        float a = __ldg(xb + (size_t)(2*p)*TD + t);
        float b = __ldg(xb + (size_t)(2*p+1)*TD + t);
        xst2[t*9 + p] = f2x2_pack(a, b);
    }
    __syncthreads();

    const int k = tid & 127;    // output channel; warp lanes = consecutive k
    const int g = tid >> 7;     // row-group: rows g*8 .. g*8+7 = pairs 4g..4g+3
    unsigned long long acc2[4];
    #pragma unroll
    for (int p = 0; p < 4; ++p) acc2[p] = 0ull;

    const float4* wp = g_wt + k;
    const int pbase = 4*g;

    #pragma unroll 4
    for (int t4 = 0; t4 < TD/4; ++t4) {
        float4 w = __ldg(&wp[(size_t)t4*HH]);   // coalesced 512B/warp
        const unsigned long long* xr = &xst2[(4*t4)*9 + pbase];
        unsigned long long wd;
        wd = f2x2_dup(w.x);
        #pragma unroll
        for (int p = 0; p < 4; ++p) f2x2_fma(acc2[p], wd, xr[p]);
        wd = f2x2_dup(w.y);
        #pragma unroll
        for (int p = 0; p < 4; ++p) f2x2_fma(acc2[p], wd, xr[9 + p]);
        wd = f2x2_dup(w.z);
        #pragma unroll
        for (int p = 0; p < 4; ++p) f2x2_fma(acc2[p], wd, xr[18 + p]);
        wd = f2x2_dup(w.w);
        #pragma unroll
        for (int p = 0; p < 4; ++p) f2x2_fma(acc2[p], wd, xr[27 + p]);
    }
    float bias = __ldg(&fcb[k]);
    #pragma unroll
    for (int p = 0; p < 4; ++p) {
        float lo, hi;
        f2x2_unpack(acc2[p], lo, hi);
        hs[(g*8 + 2*p    )*HH + k] = lo + bias;
        hs[(g*8 + 2*p + 1)*HH + k] = hi + bias;
    }
    __syncthreads();

    // LayerNorm + r/c dot products: warp w handles rows 2w, 2w+1
    const int wid = tid >> 5, lane = tid & 31;
    const float attb0 = __ldg(attb);
    const float4* lng4 = (const float4*)lng;
    const float4* lnb4 = (const float4*)lnb;
    const float4* wrv  = (const float4*)attw;          // w_row
    const float4* wcv  = (const float4*)(attw + HH);   // w_col

    #pragma unroll
    for (int rr = wid*2; rr < wid*2 + 2; ++rr) {
        float4 v = *(const float4*)&hs[rr*HH + lane*4];
        float s = v.x + v.y + v.z + v.w;
        #pragma unroll
        for (int o = 16; o; o >>= 1) s += __shfl_xor_sync(0xffffffffu, s, o);
        float mu = s * (1.0f/HH);
        float dx = v.x - mu, dy = v.y - mu, dz = v.z - mu, dw = v.w - mu;
        float q = dx*dx + dy*dy + dz*dz + dw*dw;
        #pragma unroll
        for (int o = 16; o; o >>= 1) q += __shfl_xor_sync(0xffffffffu, q, o);
        float rstd = rsqrtf(q * (1.0f/HH) + 1e-5f);
        float4 gg = __ldg(&lng4[lane]);
        float4 bb = __ldg(&lnb4[lane]);
        float4 n;
        n.x = fmaf(gg.x * dx, rstd, bb.x);
        n.y = fmaf(gg.y * dy, rstd, bb.y);
        n.z = fmaf(gg.z * dz, rstd, bb.z);
        n.w = fmaf(gg.w * dw, rstd, bb.w);
        *(float4*)&g_h[(row0 + rr)*HH + lane*4] = n;

        float4 a = __ldg(&wrv[lane]);
        float4 b2 = __ldg(&wcv[lane]);
        float rp = n.x*a.x + n.y*a.y + n.z*a.z + n.w*a.w;
        float cp = n.x*b2.x + n.y*b2.y + n.z*b2.z + n.w*b2.w;
        #pragma unroll
        for (int o = 16; o; o >>= 1) {
            rp += __shfl_xor_sync(0xffffffffu, rp, o);
            cp += __shfl_xor_sync(0xffffffffu, cp, o);
        }
        if (lane == 0) {
            g_r[row0 + rr] = rp;
            g_c[row0 + rr] = cp + attb0;
        }
    }
}

// ============================================================
// K2: rmax + hybrid reg/shfl bitonic sort + tree Z scans
// grid: B blocks, 1024 threads; thread owns elements 2tid, 2tid+1
// ============================================================
__device__ __forceinline__ unsigned int f2mono(float f) {
    unsigned int u = __float_as_uint(f);
    return (u & 0x80000000u) ? ~u : (u | 0x80000000u);
}
__device__ __forceinline__ float mono2f(unsigned int u) {
    unsigned int b = (u & 0x80000000u) ? (u ^ 0x80000000u) : ~u;
    return __uint_as_float(b);
}
__device__ __forceinline__ unsigned long long bshfl(unsigned long long e, int up_flag,
                                                    int m, int lane) {
    unsigned long long other = __shfl_xor_sync(0xffffffffu, e, m);
    bool lower = ((lane & m) == 0);
    bool cond = (e > other) == ((up_flag != 0) == lower);
    return cond ? other : e;
}

__global__ __launch_bounds__(1024) void k_sort(void)
{
    __shared__ unsigned long long skk[NN];   // 16 KB
    __shared__ float red[32];
    __shared__ float2 wsum2[32];
    __shared__ float2 wpre2[32];
    __shared__ float2 wtot;
    const int b = blockIdx.x, tid = threadIdx.x;
    const int lane = tid & 31, wid = tid >> 5;

    float r0 = g_r[b*NN + 2*tid];
    float r1 = g_r[b*NN + 2*tid + 1];

    // rmax
    float m = fmaxf(r0, r1);
    #pragma unroll
    for (int o = 16; o; o >>= 1) m = fmaxf(m, __shfl_xor_sync(0xffffffffu, m, o));
    if (lane == 0) red[wid] = m;
    __syncthreads();
    if (tid < 32) {
        float mm = red[tid];
        #pragma unroll
        for (int o = 16; o; o >>= 1) mm = fmaxf(mm, __shfl_xor_sync(0xffffffffu, mm, o));
        if (tid == 0) { red[0] = mm; g_rmax[b] = mm; }
    }
    __syncthreads();
    const float rmax = red[0];

    unsigned long long e0 = ((unsigned long long)f2mono(r0) << 32) | (unsigned int)(2*tid);
    unsigned long long e1 = ((unsigned long long)f2mono(r1) << 32) | (unsigned int)(2*tid + 1);

    // ---- register stages kk = 2..64 (all intra-warp over 64-elem segments) ----
    #pragma unroll
    for (int kk = 2; kk <= 64; kk <<= 1) {
        const int up = ((2*tid) & kk) == 0;
        #pragma unroll
        for (int j = kk >> 1; j >= 2; j >>= 1) {
            e0 = bshfl(e0, up, j >> 1, lane);
            e1 = bshfl(e1, up, j >> 1, lane);
        }
        // j = 1: intra-thread
        if ((e0 > e1) == (up != 0)) { unsigned long long t = e0; e0 = e1; e1 = t; }
    }

    // ---- kk = 128..2048: smem passes for j>=64, then shfl tail ----
    for (int kk = 128; kk <= 2048; kk <<= 1) {
        const int up = ((2*tid) & kk) == 0;
        for (int j = kk >> 1; j >= 64; j >>= 1) {
            skk[2*tid] = e0; skk[2*tid + 1] = e1;
            __syncthreads();
            unsigned long long p0 = skk[(2*tid) ^ j];
            unsigned long long p1 = skk[(2*tid + 1) ^ j];
            bool lower = (((2*tid) & j) == 0);
            if ((e0 > p0) == ((up != 0) == lower)) e0 = p0;
            if ((e1 > p1) == ((up != 0) == lower)) e1 = p1;
            __syncthreads();
        }
        #pragma unroll
        for (int j = 32; j >= 2; j >>= 1) {
            e0 = bshfl(e0, up, j >> 1, lane);
            e1 = bshfl(e1, up, j >> 1, lane);
        }
        if ((e0 > e1) == (up != 0)) { unsigned long long t = e0; e0 = e1; e1 = t; }
    }

    // ---- decode + exp ----
    float rv0 = mono2f((unsigned int)(e0 >> 32));
    float rv1 = mono2f((unsigned int)(e1 >> 32));
    int i0 = 2*tid, i1 = 2*tid + 1;
    g_rs[b*NN + i0] = rv0;               g_rs[b*NN + i1] = rv1;
    g_perm[b*NN + i0] = (int)(unsigned int)(e0 & 0xffffffffu);
    g_perm[b*NN + i1] = (int)(unsigned int)(e1 & 0xffffffffu);
    float F0 = expf(rv0 - rmax), F1 = expf(rv1 - rmax);
    float f0 = expf(0.01f*(rv0 - rmax)), f1 = expf(0.01f*(rv1 - rmax));
    g_F[b*NN + i0] = F0; g_F[b*NN + i1] = F1;
    g_f[b*NN + i0] = f0; g_f[b*NN + i1] = f1;

    // ---- combined tree scans: prefix(f) and prefix(F) ----
    float sf = f0 + f1, sF = F0 + F1;
    float isf = sf, isF = sF;
    #pragma unroll
    for (int o = 1; o < 32; o <<= 1) {
        float tf = __shfl_up_sync(0xffffffffu, isf, o);
        float tF = __shfl_up_sync(0xffffffffu, isF, o);
        if (lane >= o) { isf += tf; isF += tF; }
    }
    if (lane == 31) wsum2[wid] = make_float2(isf, isF);
    __syncthreads();
    if (wid == 0) {
        float2 v = wsum2[lane];
        float ax = v.x, ay = v.y;
        #pragma unroll
        for (int o = 1; o < 32; o <<= 1) {
            float tx2 = __shfl_up_sync(0xffffffffu, ax, o);
            float ty2 = __shfl_up_sync(0xffffffffu, ay, o);
            if (lane >= o) { ax += tx2; ay += ty2; }
        }
        wpre2[lane] = make_float2(ax - v.x, ay - v.y);
        if (lane == 31) wtot = make_float2(ax, ay);
    }
    __syncthreads();
    float2 off = wpre2[wid];
    float exf = off.x + isf - sf;        // exclusive prefix of f at pos 2tid
    float exF = off.y + isF - sF;        // exclusive prefix of F at pos 2tid
    float totF = wtot.y;

    g_Zneg[b*NP1 + i0 + 1] = exf + f0;
    g_Zneg[b*NP1 + i1 + 1] = exf + f0 + f1;
    g_Zpos[b*NP1 + i0] = totF - exF;
    g_Zpos[b*NP1 + i1] = totF - exF - F0;
    if (tid == 0) { g_Zneg[b*NP1] = 0.f; g_Zpos[b*NP1 + NN] = 0.f; }
}

// ============================================================
// K3a: chunk-local vector scans. grid (NC, B, 2), 128 threads
// ============================================================
__global__ __launch_bounds__(128) void k_scan(void)
{
    __shared__ int   sp[CS];
    __shared__ float sw[CS];
    const int c = blockIdx.x, b = blockIdx.y, dir = blockIdx.z;
    const int k = threadIdx.x;
    const int ub = b*NN + c*CS;
    if (k < CS) {
        sp[k] = g_perm[ub + k];
        sw[k] = dir ? g_F[ub + k] : g_f[ub + k];
    }
    __syncthreads();

    const float* hb = g_h + (size_t)b * NN * HH;
    const size_t base = ((size_t)(b*NP1) + (size_t)c*CS) * HH + k;

    if (!dir) {
        float acc = 0.f;
        #pragma unroll
        for (int v0 = 0; v0 < CS; v0 += 8) {
            float hv[8];
            #pragma unroll
            for (int q = 0; q < 8; ++q) hv[q] = __ldg(hb + (size_t)sp[v0+q]*HH + k);
            #pragma unroll
            for (int q = 0; q < 8; ++q) {
                g_Pneg[base + (size_t)(v0+q)*HH] = acc;
                acc = fmaf(sw[v0+q], hv[q], acc);
            }
        }
        g_Tneg[(b*NC + c)*HH + k] = acc;
    } else {
        float acc = 0.f;
        #pragma unroll
        for (int v0 = 0; v0 < CS; v0 += 8) {
            float hv[8];
            #pragma unroll
            for (int q = 0; q < 8; ++q) {
                int vv = CS-1-(v0+q);
                hv[q] = __ldg(hb + (size_t)sp[vv]*HH + k);
            }
            #pragma unroll
            for (int q = 0; q < 8; ++q) {
                int vv = CS-1-(v0+q);
                acc = fmaf(sw[vv], hv[q], acc);
                g_Ppos[base + (size_t)vv*HH] = acc;
            }
        }
        g_Tpos[(b*NC + c)*HH + k] = acc;
    }
}

// ============================================================
// K3b: chunk offsets. grid B, 256 threads. Batched loads + reg prefix.
// ============================================================
__global__ __launch_bounds__(256) void k_off(void)
{
    const int b = blockIdx.x, tid = threadIdx.x;
    const int k = tid & 127;
    if (tid < 128) {
        float tv[NC];
        #pragma unroll
        for (int c = 0; c < NC; ++c) tv[c] = g_Tneg[(b*NC + c)*HH + k];
        float acc = 0.f;
        #pragma unroll
        for (int c = 0; c < NC; ++c) {
            g_OffNeg[(b*(NC+1) + c)*HH + k] = acc;
            acc += tv[c];
        }
        g_OffNeg[(b*(NC+1) + NC)*HH + k] = acc;
        g_Pneg[((size_t)(b*NP1) + NN)*HH + k] = 0.f;
    } else {
        float tv[NC];
        #pragma unroll
        for (int c = 0; c < NC; ++c) tv[c] = g_Tpos[(b*NC + c)*HH + k];
        float acc = 0.f;
        g_OffPos[(b*(NC+1) + NC)*HH + k] = 0.f;
        #pragma unroll
        for (int c = NC-1; c >= 0; --c) {
            g_OffPos[(b*(NC+1) + c)*HH + k] = acc;
            acc += tv[c];
        }
        g_Ppos[((size_t)(b*NP1) + NN)*HH + k] = 0.f;
    }
}

// ============================================================
// K4: output. grid B*N blocks, 128 threads (one row each)
// ============================================================
__global__ __launch_bounds__(128) void k_out(float* __restrict__ out)
{
    const int row = blockIdx.x;
    const int b = row >> 11;
    const int k = threadIdx.x;

    const float cv   = g_c[row];
    const float rmax = g_rmax[b];
    const float* rs  = g_rs + b*NN;
    const float thr  = -cv;

    int lo = 0, hi = NN;
    while (lo < hi) {
        int mid = (lo + hi) >> 1;
        if (rs[mid] < thr) lo = mid + 1; else hi = mid;
    }
    const int t = lo;

    const float a1 = cv + rmax;
    const float S  = fmaxf(a1, 0.f);
    const float E  = expf(a1 - S);
    const float e2 = expf(fmaf(0.01f, a1, -S));
    const float den = E * g_Zpos[b*NP1 + t] + e2 * g_Zneg[b*NP1 + t];
    const float inv = 1.0f / den;
    const float cA = E * inv, cB = e2 * inv;

    const int ch = t >> 5;  // t / CS
    const size_t base = ((size_t)(b*NP1) + t) * HH + k;
    const int obase = (b*(NC+1) + ch)*HH + k;
    const float pp = g_Ppos[base] + g_OffPos[obase];
    const float pn = g_Pneg[base] + g_OffNeg[obase];
    out[(size_t)row*HH + k] = fmaf(cA, pp, cB * pn);
}

// ============================================================
extern "C" void kernel_launch(void* const* d_in, const int* in_sizes, int n_in,
                              void* d_out, int out_size)
{
    const float* x    = (const float*)d_in[0];
    const float* fcw  = (const float*)d_in[1];
    const float* fcb  = (const float*)d_in[2];
    const float* attw = (const float*)d_in[3];
    const float* attb = (const float*)d_in[4];
    const float* lng  = (const float*)d_in[5];
    const float* lnb  = (const float*)d_in[6];
    float* out = (float*)d_out;

    k_wt<<<dim3(4,4), dim3(32,8)>>>(fcw);
    k_fc_ln<<<(BB*NN)/RPB, 256>>>(x, fcb, attw, attb, lng, lnb);
    k_sort<<<BB, 1024>>>();
    k_scan<<<dim3(NC, BB, 2), 128>>>();
    k_off<<<BB, 256>>>();
    k_out<<<BB*NN, 128>>>(out);
}